// round 1
// baseline (speedup 1.0000x reference)
#include <cuda_runtime.h>

typedef unsigned long long ull;

#define NROWS 16384
#define DIMP  1024
#define NCLS  10
#define IMG   784

// Normalized reference states (scratch: __device__ global, no allocation).
__device__ float g_ref[NCLS * DIMP];

// ---------- f32x2 helpers (Blackwell packed fp32) ----------
__device__ __forceinline__ ull pack2(float lo, float hi) {
    ull r;
    asm("mov.b64 %0, {%1, %2};" : "=l"(r) : "f"(lo), "f"(hi));
    return r;
}
__device__ __forceinline__ void unpack2(ull v, float& lo, float& hi) {
    asm("mov.b64 {%0, %1}, %2;" : "=f"(lo), "=f"(hi) : "l"(v));
}
__device__ __forceinline__ void fma2(ull& acc, ull a, ull b) {
    asm("fma.rn.f32x2 %0, %1, %2, %0;" : "+l"(acc) : "l"(a), "l"(b));
}
__device__ __forceinline__ void add2(ull& acc, ull a) {
    asm("add.rn.f32x2 %0, %1, %0;" : "+l"(acc) : "l"(a));
}

// ---------- prologue: pad + L2-normalize canon -> g_ref ----------
__global__ void ref_norm_kernel(const float* __restrict__ canon) {
    __shared__ float buf[DIMP];
    __shared__ float wsum[8];
    __shared__ float inv;
    int c = blockIdx.x, t = threadIdx.x;
    float ps = 0.f;
    for (int i = t; i < DIMP; i += 256) {
        float v = (i < IMG) ? canon[c * IMG + i] : 0.f;
        buf[i] = v;
        ps += v * v;
    }
    #pragma unroll
    for (int o = 16; o; o >>= 1) ps += __shfl_xor_sync(0xFFFFFFFFu, ps, o);
    if ((t & 31) == 0) wsum[t >> 5] = ps;
    __syncthreads();
    if (t == 0) {
        float s = 0.f;
        #pragma unroll
        for (int i = 0; i < 8; i++) s += wsum[i];
        inv = 1.0f / sqrtf(s);
    }
    __syncthreads();
    float iv = inv;
    for (int i = t; i < DIMP; i += 256)
        g_ref[c * DIMP + i] = buf[i] * iv;
}

// ---------- main: [16384,1024] x [1024,10] twice, fused |.|^2 ----------
// 128 threads = 4 warps; each warp handles 4 rows (row-pair f32x2 packing);
// block = 16 rows; grid = 1024 blocks.
__global__ __launch_bounds__(128, 3) void swap_test_kernel(
    const float* __restrict__ zre, const float* __restrict__ zim,
    float* __restrict__ out) {

    __shared__ __align__(16) union SM {
        float ref[NCLS * DIMP];   // 40960 B  (main-loop phase)
        ull   red[160 * 33];      // 42240 B  (epilogue phase, overlaid)
    } sm;

    const int tid = threadIdx.x;

    // stage ref into smem (float4 copy)
    {
        const float4* g4 = (const float4*)g_ref;
        float4* s4 = (float4*)sm.ref;
        for (int i = tid; i < NCLS * DIMP / 4; i += 128) s4[i] = g4[i];
    }
    __syncthreads();

    const int lane = tid & 31;
    const int w    = tid >> 5;
    const size_t rowBase = (size_t)blockIdx.x * 16 + (size_t)w * 4;
    const float4* zr = (const float4*)zre + rowBase * (DIMP / 4);
    const float4* zi = (const float4*)zim + rowBase * (DIMP / 4);
    const float4* rf = (const float4*)sm.ref;

    // acc[c][pair][re/im] : f32x2 holds (row_even, row_odd) partial sums
    ull acc[NCLS][2][2];
    #pragma unroll
    for (int c = 0; c < NCLS; c++)
        #pragma unroll
        for (int p = 0; p < 2; p++) {
            acc[c][p][0] = 0ull;
            acc[c][p][1] = 0ull;
        }

    #pragma unroll 2
    for (int k = 0; k < 8; k++) {
        const int di = k * 32 + lane;           // float4 index within a row
        float4 a0 = zr[di];                     // row0 re
        float4 a1 = zr[256 + di];               // row1 re
        float4 a2 = zr[512 + di];               // row2 re
        float4 a3 = zr[768 + di];               // row3 re
        float4 b0 = zi[di];
        float4 b1 = zi[256 + di];
        float4 b2 = zi[512 + di];
        float4 b3 = zi[768 + di];

        // row-pair packs, one per d-slot
        ull re0[4], re1[4], im0[4], im1[4];
        re0[0] = pack2(a0.x, a1.x); re0[1] = pack2(a0.y, a1.y);
        re0[2] = pack2(a0.z, a1.z); re0[3] = pack2(a0.w, a1.w);
        re1[0] = pack2(a2.x, a3.x); re1[1] = pack2(a2.y, a3.y);
        re1[2] = pack2(a2.z, a3.z); re1[3] = pack2(a2.w, a3.w);
        im0[0] = pack2(b0.x, b1.x); im0[1] = pack2(b0.y, b1.y);
        im0[2] = pack2(b0.z, b1.z); im0[3] = pack2(b0.w, b1.w);
        im1[0] = pack2(b2.x, b3.x); im1[1] = pack2(b2.y, b3.y);
        im1[2] = pack2(b2.z, b3.z); im1[3] = pack2(b2.w, b3.w);

        #pragma unroll
        for (int c = 0; c < NCLS; c++) {
            float4 f = rf[c * 256 + di];
            ull fd;
            fd = pack2(f.x, f.x);
            fma2(acc[c][0][0], re0[0], fd); fma2(acc[c][1][0], re1[0], fd);
            fma2(acc[c][0][1], im0[0], fd); fma2(acc[c][1][1], im1[0], fd);
            fd = pack2(f.y, f.y);
            fma2(acc[c][0][0], re0[1], fd); fma2(acc[c][1][0], re1[1], fd);
            fma2(acc[c][0][1], im0[1], fd); fma2(acc[c][1][1], im1[1], fd);
            fd = pack2(f.z, f.z);
            fma2(acc[c][0][0], re0[2], fd); fma2(acc[c][1][0], re1[2], fd);
            fma2(acc[c][0][1], im0[2], fd); fma2(acc[c][1][1], im1[2], fd);
            fd = pack2(f.w, f.w);
            fma2(acc[c][0][0], re0[3], fd); fma2(acc[c][1][0], re1[3], fd);
            fma2(acc[c][0][1], im0[3], fd); fma2(acc[c][1][1], im1[3], fd);
        }
    }

    __syncthreads();   // all warps done reading sm.ref -> safe to overlay

    // write lane partials: m = w*40 + s*20 + c*2 + p  (parity-spread layout)
    #pragma unroll
    for (int c = 0; c < NCLS; c++)
        #pragma unroll
        for (int p = 0; p < 2; p++) {
            sm.red[(w * 40 +      c * 2 + p) * 33 + lane] = acc[c][p][0];
            sm.red[(w * 40 + 20 + c * 2 + p) * 33 + lane] = acc[c][p][1];
        }
    __syncthreads();

    // 80 tasks: (warp, c, pair) -> two output rows each
    if (tid < 80) {
        const int w2 = tid / 20;
        const int q  = tid % 20;
        const int c  = q >> 1;
        const int p  = q & 1;
        const int mRe = w2 * 40 + c * 2 + p;
        const int mIm = mRe + 20;
        ull sre = 0ull, sim = 0ull;
        #pragma unroll
        for (int j = 0; j < 32; j++) {
            add2(sre, sm.red[mRe * 33 + j]);
            add2(sim, sm.red[mIm * 33 + j]);
        }
        float reL, reH, imL, imH;
        unpack2(sre, reL, reH);
        unpack2(sim, imL, imH);
        const size_t row = (size_t)blockIdx.x * 16 + (size_t)w2 * 4 + (size_t)p * 2;
        out[row * NCLS + c]       = reL * reL + imL * imL;
        out[(row + 1) * NCLS + c] = reH * reH + imH * imH;
    }
}

extern "C" void kernel_launch(void* const* d_in, const int* in_sizes, int n_in,
                              void* d_out, int out_size) {
    const float* zre   = (const float*)d_in[0];
    const float* zim   = (const float*)d_in[1];
    const float* canon = (const float*)d_in[2];
    float* out = (float*)d_out;

    ref_norm_kernel<<<NCLS, 256>>>(canon);
    swap_test_kernel<<<NROWS / 16, 128>>>(zre, zim, out);
}

// round 4
// speedup vs baseline: 1.5161x; 1.5161x over previous
#include <cuda_runtime.h>

typedef unsigned long long ull;

#define NROWS   16384
#define DIMP    1024
#define NCLS    10
#define IMG     784
#define QSTRIDE 22              // ull per d-quad group in smem: 20 data + 2 pad (176 B)

// Packed reference pairs (prologue output), dense layout:
// g_refp[(d>>2)*20 + p*4 + (d&3)] = ( ref[2p][d], ref[2p+1][d] )
__device__ ull g_refp[256 * 20];

// ---------- f32x2 helpers ----------
__device__ __forceinline__ ull pack2(float lo, float hi) {
    ull r;
    asm("mov.b64 %0, {%1, %2};" : "=l"(r) : "f"(lo), "f"(hi));
    return r;
}
__device__ __forceinline__ void unpack2(ull v, float& lo, float& hi) {
    asm("mov.b64 {%0, %1}, %2;" : "=f"(lo), "=f"(hi) : "l"(v));
}
__device__ __forceinline__ void fma2(ull& acc, ull a, ull b) {
    asm("fma.rn.f32x2 %0, %1, %2, %0;" : "+l"(acc) : "l"(a), "l"(b));
}
__device__ __forceinline__ void add2(ull& acc, ull a) {
    asm("add.rn.f32x2 %0, %1, %0;" : "+l"(acc) : "l"(a));
}

// ---------- prologue: block p normalizes classes 2p, 2p+1 and writes packed pairs ----------
__global__ void ref_pack_kernel(const float* __restrict__ canon) {
    __shared__ float v0[DIMP], v1[DIMP];
    __shared__ float wred[16];
    __shared__ float invs[2];
    const int p = blockIdx.x, t = threadIdx.x;
    const float* c0 = canon + (2 * p) * IMG;
    const float* c1 = canon + (2 * p + 1) * IMG;
    float s0 = 0.f, s1 = 0.f;
    for (int i = t; i < DIMP; i += 256) {
        float a = (i < IMG) ? c0[i] : 0.f;
        float b = (i < IMG) ? c1[i] : 0.f;
        v0[i] = a; v1[i] = b;
        s0 += a * a; s1 += b * b;
    }
    #pragma unroll
    for (int o = 16; o; o >>= 1) {
        s0 += __shfl_xor_sync(0xFFFFFFFFu, s0, o);
        s1 += __shfl_xor_sync(0xFFFFFFFFu, s1, o);
    }
    if ((t & 31) == 0) { wred[t >> 5] = s0; wred[8 + (t >> 5)] = s1; }
    __syncthreads();
    if (t == 0) {
        float a = 0.f, b = 0.f;
        #pragma unroll
        for (int i = 0; i < 8; i++) { a += wred[i]; b += wred[8 + i]; }
        invs[0] = 1.0f / sqrtf(a);
        invs[1] = 1.0f / sqrtf(b);
    }
    __syncthreads();
    const float i0 = invs[0], i1 = invs[1];
    for (int d = t; d < DIMP; d += 256)
        g_refp[(d >> 2) * 20 + p * 4 + (d & 3)] = pack2(v0[d] * i0, v1[d] * i1);
}

// ---------- main kernel ----------
// 256 threads = 8 warps, 2 rows per warp -> 16 rows/block, grid = 1024.
// acc A[p*4 + row*2 + arr] : f32x2 holds (sum_{class 2p}, sum_{class 2p+1}).
__global__ __launch_bounds__(256, 2) void swap_test_kernel(
    const float* __restrict__ zre, const float* __restrict__ zim,
    float* __restrict__ out) {

    __shared__ __align__(16) ull sm[256 * QSTRIDE];   // 45056 B

    const int tid = threadIdx.x;

    // stage packed ref into smem, inserting 16 B pad per 160 B data group
    {
        const float4* g4 = (const float4*)g_refp;
        for (int c = tid; c < 2560; c += 256) {
            const int q = c / 10;
            const int r = c - q * 10;
            *((float4*)((char*)sm + q * (QSTRIDE * 8) + r * 16)) = g4[c];
        }
    }
    __syncthreads();

    const int lane = tid & 31;
    const int w    = tid >> 5;
    const size_t rowBase = (size_t)blockIdx.x * 16 + (size_t)w * 2;
    const float4* zr = (const float4*)zre + rowBase * 256;
    const float4* zi = (const float4*)zim + rowBase * 256;
    const char* rp = (const char*)sm + (size_t)lane * (QSTRIDE * 8);

    ull A[20];
    #pragma unroll
    for (int i = 0; i < 20; i++) A[i] = 0ull;

    float4 c0 = zr[lane], c1 = zr[256 + lane];
    float4 c2 = zi[lane], c3 = zi[256 + lane];

    #pragma unroll
    for (int k = 0; k < 8; k++) {
        float4 n0, n1, n2, n3;
        if (k < 7) {
            const int di = (k + 1) * 32 + lane;
            n0 = zr[di]; n1 = zr[256 + di];
            n2 = zi[di]; n3 = zi[256 + di];
        }

        // duplicate z scalars into f32x2 operands (reused across 5 class-pairs)
        ull d0[4], d1[4], d2[4], d3[4];
        d0[0] = pack2(c0.x, c0.x); d0[1] = pack2(c0.y, c0.y);
        d0[2] = pack2(c0.z, c0.z); d0[3] = pack2(c0.w, c0.w);
        d1[0] = pack2(c1.x, c1.x); d1[1] = pack2(c1.y, c1.y);
        d1[2] = pack2(c1.z, c1.z); d1[3] = pack2(c1.w, c1.w);
        d2[0] = pack2(c2.x, c2.x); d2[1] = pack2(c2.y, c2.y);
        d2[2] = pack2(c2.z, c2.z); d2[3] = pack2(c2.w, c2.w);
        d3[0] = pack2(c3.x, c3.x); d3[1] = pack2(c3.y, c3.y);
        d3[2] = pack2(c3.z, c3.z); d3[3] = pack2(c3.w, c3.w);

        const char* rk = rp + k * (32 * QSTRIDE * 8);
        #pragma unroll
        for (int p = 0; p < 5; p++) {
            ulonglong2 fa = *(const ulonglong2*)(rk + p * 32);
            ulonglong2 fb = *(const ulonglong2*)(rk + p * 32 + 16);
            // row0 re
            fma2(A[p * 4 + 0], d0[0], fa.x); fma2(A[p * 4 + 0], d0[1], fa.y);
            fma2(A[p * 4 + 0], d0[2], fb.x); fma2(A[p * 4 + 0], d0[3], fb.y);
            // row0 im
            fma2(A[p * 4 + 1], d2[0], fa.x); fma2(A[p * 4 + 1], d2[1], fa.y);
            fma2(A[p * 4 + 1], d2[2], fb.x); fma2(A[p * 4 + 1], d2[3], fb.y);
            // row1 re
            fma2(A[p * 4 + 2], d1[0], fa.x); fma2(A[p * 4 + 2], d1[1], fa.y);
            fma2(A[p * 4 + 2], d1[2], fb.x); fma2(A[p * 4 + 2], d1[3], fb.y);
            // row1 im
            fma2(A[p * 4 + 3], d3[0], fa.x); fma2(A[p * 4 + 3], d3[1], fa.y);
            fma2(A[p * 4 + 3], d3[2], fb.x); fma2(A[p * 4 + 3], d3[3], fb.y);
        }

        if (k < 7) { c0 = n0; c1 = n1; c2 = n2; c3 = n3; }
    }

    __syncthreads();   // all warps done with staged ref -> overlay reduction buffer

    // lane partials: 8 warps x 20 ull rows, stride 33 (bank-conflict-free STS.64)
    ull* red = sm;
    #pragma unroll
    for (int i = 0; i < 20; i++)
        red[(w * 20 + i) * 33 + lane] = A[i];
    __syncthreads();

    // 80 tasks: (warp w2, class-pair p, row j) -> 2 outputs each
    if (tid < 80) {
        const int w2 = tid / 10;
        const int q  = tid % 10;
        const int p  = q >> 1;
        const int j  = q & 1;
        const int mRe = w2 * 20 + p * 4 + j * 2;
        ull sre = 0ull, sim = 0ull;
        #pragma unroll
        for (int x = 0; x < 32; x++) {
            add2(sre, red[mRe * 33 + x]);
            add2(sim, red[(mRe + 1) * 33 + x]);
        }
        float reL, reH, imL, imH;
        unpack2(sre, reL, reH);
        unpack2(sim, imL, imH);
        const size_t row = (size_t)blockIdx.x * 16 + (size_t)w2 * 2 + (size_t)j;
        out[row * NCLS + 2 * p]     = reL * reL + imL * imL;
        out[row * NCLS + 2 * p + 1] = reH * reH + imH * imH;
    }
}

extern "C" void kernel_launch(void* const* d_in, const int* in_sizes, int n_in,
                              void* d_out, int out_size) {
    const float* zre   = (const float*)d_in[0];
    const float* zim   = (const float*)d_in[1];
    const float* canon = (const float*)d_in[2];
    float* out = (float*)d_out;

    ref_pack_kernel<<<NCLS / 2, 256>>>(canon);
    swap_test_kernel<<<NROWS / 16, 256>>>(zre, zim, out);
}